// round 7
// baseline (speedup 1.0000x reference)
#include <cuda_runtime.h>

// Problem shape (fixed by the dataset)
#define TT 4096
#define NB 16
#define CC 512
#define NC (NB * CC)            // 8192 columns
#define TOTAL (TT * NC)         // 33,554,432 floats for new_x

#define CHUNK 64                // rows per scan-thread (global chunk granularity)
#define NCH (TT / CHUNK)        // 64 global chunks
#define NSEG 4
#define CPSEG (NCH / NSEG)      // 16 chunks per segment (32 MB, L2-resident)
#define SEG_BLOCKS ((CPSEG * NC) / 256)   // 512 blocks per role
#define RCP_BLOCKS ((TT * NB) / 256)      // 256

// Static scratch (no allocations; fully rewritten every replay — graph-safe)
__device__ float g_agg[NCH * NC];   // 2 MB: per-(chunk, col) sums, L2-resident
__device__ float g_rcp[TT * NB];    // 256 KB: 1/(t+1+len_n), layout [t][n]

// Sum role: per-(chunk, col) partial sums for 16 chunks of one segment.
// __ldcg keeps the streamed segment resident in L2 for the next launch's re-read.
__device__ __forceinline__ void sum_role(const float* __restrict__ x, int idx, int s) {
    int nc = idx & (NC - 1);
    int gc = s * CPSEG + (idx >> 13);
    const float* p = x + (size_t)gc * CHUNK * NC + nc;
    float ssum = 0.0f;
#pragma unroll 8
    for (int i = 0; i < CHUNK; i++) ssum += __ldcg(p + (size_t)i * NC);
    g_agg[gc * NC + nc] = ssum;
}

// kA: segment-0 sums + reciprocal table (role split by blockIdx).
__global__ void __launch_bounds__(256)
kA(const float* __restrict__ x, const int* __restrict__ cached_len) {
    int bid = blockIdx.x, tid = threadIdx.x;
    if (bid < SEG_BLOCKS) {
        sum_role(x, bid * 256 + tid, 0);
    } else {
        int idx = (bid - SEG_BLOCKS) * 256 + tid;      // 0 .. TT*NB-1
        int n = idx & (NB - 1);
        int t = idx >> 4;
        g_rcp[idx] = 1.0f / ((float)(t + 1) + (float)cached_len[n]);
    }
}

// kC(s): low blocks = final scan of segment s (x[s] L2-hot, prefix summed
// per-thread from g_agg); high blocks = sum role for segment s+1 (DRAM stream).
__global__ void __launch_bounds__(256)
kC(const float* __restrict__ x, const int* __restrict__ cached_len,
   const float* __restrict__ cached_avg, float* __restrict__ out,
   int s, int extras) {
    int bid = blockIdx.x, tid = threadIdx.x;
    if (bid >= SEG_BLOCKS) {                            // pre-sum next segment
        sum_role(x, (bid - SEG_BLOCKS) * 256 + tid, s + 1);
        return;
    }
    // Scan role for segment s.
    int idx = bid * 256 + tid;
    int nc = idx & (NC - 1);
    int gc = s * CPSEG + (idx >> 13);                   // uniform within block
    int n = nc >> 9;                                    // c fastest, C=512

    // Exclusive base: seed + predecessor chunk aggregates (independent,
    // coalesced L2 loads — no serial scan kernel).
    float run = cached_avg[nc] * (float)cached_len[n];
#pragma unroll 8
    for (int ch = 0; ch < gc; ch++) run += g_agg[ch * NC + nc];

    const float* px = x    + (size_t)gc * CHUNK * NC + nc;
    float*       po = out  + (size_t)gc * CHUNK * NC + nc;
    const float* pr = g_rcp + (size_t)gc * CHUNK * NB + n;   // warp-uniform

    float last = 0.0f;
#pragma unroll 8
    for (int i = 0; i < CHUNK; i++) {
        run += __ldcs(px + (size_t)i * NC);             // evict-first: x[s] is dead after this
        last = run * pr[(size_t)i * NB];
        __stcs(po + (size_t)i * NC, last);              // streaming store
    }

    if (extras && s == NSEG - 1) {
        // Tuple order: [new_x | new_cached_len (as float) | new_cached_avg]
        if (gc == NCH - 1) out[TOTAL + NB + nc] = last;         // new_x[T-1]
        if (idx < NB) out[TOTAL + idx] = (float)(cached_len[idx] + TT);
    }
}

extern "C" void kernel_launch(void* const* d_in, const int* in_sizes, int n_in,
                              void* d_out, int out_size) {
    const float* x          = (const float*)d_in[0];   // (T, N, C)
    const int*   cached_len = (const int*)d_in[1];     // (N,)
    const float* cached_avg = (const float*)d_in[2];   // (N, C)
    float* out = (float*)d_out;

    int extras = (out_size >= TOTAL + NB + NC) ? 1 : 0;

    kA<<<SEG_BLOCKS + RCP_BLOCKS, 256>>>(x, cached_len);
    for (int s = 0; s < NSEG; s++) {
        int nblk = (s < NSEG - 1) ? 2 * SEG_BLOCKS : SEG_BLOCKS;
        kC<<<nblk, 256>>>(x, cached_len, cached_avg, out, s, extras);
    }
}

// round 8
// speedup vs baseline: 1.7444x; 1.7444x over previous
#include <cuda_runtime.h>

// Problem shape (fixed by the dataset)
#define TT 4096
#define NB 16
#define CC 512
#define NC (NB * CC)            // 8192 columns
#define NC4 (NC / 4)            // 2048 float4 columns
#define TOTAL (TT * NC)         // 33,554,432 floats for new_x

#define NSEG 4
#define SEG_T (TT / NSEG)       // 1024 rows/segment = 32 MB (L2-resident)
#define CHUNK 16                // rows per thread
#define CPS (SEG_T / CHUNK)     // 64 chunks per segment
#define NCH (TT / CHUNK)        // 256 chunks total
#define SEG_BLOCKS ((CPS * NC4) / 256)   // 512 blocks per segment role
#define RCP_BLOCKS ((TT * NB) / 256)     // 256

// Static scratch (no allocations; fully rewritten every replay — graph-safe)
__device__ float4 g_agg[NCH * NC4];    // 8 MB: per-(chunk, col4) sums
__device__ float4 g_base[NCH * NC4];   // 8 MB: exclusive bases (seeded)
__device__ float4 g_carry[NC4];        // 32 KB: carry across segments
__device__ float  g_rcp[TT * NB];      // 256 KB: 1/(t+1+len_n), [t][n]

__device__ __forceinline__ float4 f4add(float4 a, float4 b) {
    return make_float4(a.x + b.x, a.y + b.y, a.z + b.z, a.w + b.w);
}
__device__ __forceinline__ float4 f4shfl_up(float4 v, int off) {
    v.x = __shfl_up_sync(0xffffffffu, v.x, off);
    v.y = __shfl_up_sync(0xffffffffu, v.y, off);
    v.z = __shfl_up_sync(0xffffffffu, v.z, off);
    v.w = __shfl_up_sync(0xffffffffu, v.w, off);
    return v;
}

__device__ __forceinline__ void sum_chunk(const float4* __restrict__ x4,
                                          int gc, int nc4) {
    const float4* p = x4 + (size_t)gc * CHUNK * NC4 + nc4;
    float4 s = make_float4(0.f, 0.f, 0.f, 0.f);
#pragma unroll
    for (int i = 0; i < CHUNK; i++) s = f4add(s, p[(size_t)i * NC4]);
    g_agg[gc * NC4 + nc4] = s;
}

// kA: segment-0 partial sums + reciprocal table (role split by blockIdx).
__global__ void __launch_bounds__(256)
kA(const float4* __restrict__ x4, const int* __restrict__ cached_len) {
    int bid = blockIdx.x, tid = threadIdx.x;
    if (bid < SEG_BLOCKS) {
        int idx = bid * 256 + tid;
        sum_chunk(x4, idx >> 11, idx & (NC4 - 1));     // gc = chunk-local (seg 0)
    } else {
        int idx = (bid - SEG_BLOCKS) * 256 + tid;      // 0 .. TT*NB-1
        int n = idx & (NB - 1);
        int t = idx >> 4;
        g_rcp[idx] = 1.0f / ((float)(t + 1) + (float)cached_len[n]);
    }
}

// kscan(s): warp-per-column scan of the segment's 64 chunk aggregates.
// Chain length: 2 L2 loads + 5 shfl steps (vs 64 dependent L2 loads in R6).
__global__ void __launch_bounds__(256)
kscan(const int* __restrict__ cached_len, const float4* __restrict__ avg4, int s) {
    int warp = (blockIdx.x * 256 + threadIdx.x) >> 5;   // 0 .. NC4-1
    int lane = threadIdx.x & 31;
    int col4 = warp;

    float4 carry;
    if (s == 0) {
        float lenf = (float)cached_len[col4 >> 7];
        float4 a = avg4[col4];
        carry = make_float4(a.x * lenf, a.y * lenf, a.z * lenf, a.w * lenf);
    } else {
        carry = g_carry[col4];
    }

    int gc0 = s * CPS;
    float4 a0 = g_agg[(gc0 + 2 * lane)     * NC4 + col4];
    float4 a1 = g_agg[(gc0 + 2 * lane + 1) * NC4 + col4];
    float4 loc = f4add(a0, a1);

    float4 incl = loc;
#pragma unroll
    for (int off = 1; off < 32; off <<= 1) {
        float4 up = f4shfl_up(incl, off);
        if (lane >= off) incl = f4add(incl, up);
    }
    float4 excl = f4shfl_up(incl, 1);
    if (lane == 0) excl = make_float4(0.f, 0.f, 0.f, 0.f);

    float4 b0 = f4add(carry, excl);
    float4 b1 = f4add(b0, a0);
    g_base[(gc0 + 2 * lane)     * NC4 + col4] = b0;
    g_base[(gc0 + 2 * lane + 1) * NC4 + col4] = b1;
    if (lane == 31) g_carry[col4] = f4add(carry, incl);
}

// kC(s): low blocks = final scan of segment s (x[s] L2-hot from previous
// launch); high blocks = partial sums of segment s+1 (DRAM streaming,
// overlapped). Independent roles, stream-ordered deps only.
__global__ void __launch_bounds__(256)
kC(const float4* __restrict__ x4, const int* __restrict__ cached_len,
   float4* __restrict__ out4, int s, int extras) {
    int bid = blockIdx.x, tid = threadIdx.x;
    if (bid >= SEG_BLOCKS) {                            // sum role: segment s+1
        int idx = (bid - SEG_BLOCKS) * 256 + tid;
        sum_chunk(x4, (s + 1) * CPS + (idx >> 11), idx & (NC4 - 1));
        return;
    }
    // scan role: segment s
    int idx = bid * 256 + tid;
    int nc4 = idx & (NC4 - 1);
    int gc = s * CPS + (idx >> 11);
    int n = nc4 >> 7;                                   // (nc4*4)/512, warp-uniform

    float4 run = g_base[gc * NC4 + nc4];
    const float4* px = x4   + (size_t)gc * CHUNK * NC4 + nc4;
    float4*       po = out4 + (size_t)gc * CHUNK * NC4 + nc4;
    const float*  pr = g_rcp + (size_t)gc * CHUNK * NB + n;

    float4 last = make_float4(0.f, 0.f, 0.f, 0.f);
#pragma unroll
    for (int i = 0; i < CHUNK; i++) {
        float4 v = px[(size_t)i * NC4];
        run = f4add(run, v);
        float r = pr[(size_t)i * NB];
        last.x = run.x * r; last.y = run.y * r;
        last.z = run.z * r; last.w = run.w * r;
        po[(size_t)i * NC4] = last;
    }

    if (extras && s == NSEG - 1) {
        // Tuple order: [new_x | new_cached_len (as float) | new_cached_avg]
        if ((idx >> 11) == CPS - 1)
            out4[(TOTAL + NB) / 4 + nc4] = last;        // new_x[T-1]
        if (idx < NB) {
            float* outf = (float*)out4;
            outf[TOTAL + idx] = (float)(cached_len[idx] + TT);
        }
    }
}

extern "C" void kernel_launch(void* const* d_in, const int* in_sizes, int n_in,
                              void* d_out, int out_size) {
    const float4* x4         = (const float4*)d_in[0];   // (T, N, C)
    const int*    cached_len = (const int*)d_in[1];      // (N,)
    const float4* avg4       = (const float4*)d_in[2];   // (N, C)
    float4* out4 = (float4*)d_out;

    int extras = (out_size >= TOTAL + NB + NC) ? 1 : 0;

    kA<<<SEG_BLOCKS + RCP_BLOCKS, 256>>>(x4, cached_len);
    for (int s = 0; s < NSEG; s++) {
        kscan<<<(NC4 * 32) / 256, 256>>>(cached_len, avg4, s);
        int nblk = (s < NSEG - 1) ? 2 * SEG_BLOCKS : SEG_BLOCKS;
        kC<<<nblk, 256>>>(x4, cached_len, out4, s, extras);
    }
}

// round 9
// speedup vs baseline: 1.9005x; 1.0895x over previous
#include <cuda_runtime.h>

// Problem shape (fixed by the dataset)
#define TT 4096
#define NB 16
#define CC 512
#define NC (NB * CC)            // 8192 columns
#define NC4 (NC / 4)            // 2048 float4 columns
#define TOTAL (TT * NC)         // 33,554,432 floats for new_x

#define NSEG 4
#define SEG_T (TT / NSEG)       // 1024 rows/segment = 32 MB (L2-resident)
#define CHUNK 16                // rows per thread
#define CPS (SEG_T / CHUNK)     // 64 chunks per segment
#define NCH (TT / CHUNK)        // 256 chunks total
#define ROLE_BLOCKS ((CPS * NC4) / 256)   // 512 blocks for sum/scan roles
#define KSCAN_BLOCKS ((NC4 * 32) / 256)   // 256 blocks (warp per col4)
#define RCP_BLOCKS ((TT * NB) / 256)      // 256

// Static scratch (no allocations; fully rewritten every replay — graph-safe)
__device__ float4 g_agg[NCH * NC4];    // 8 MB: per-(chunk, col4) sums
__device__ float4 g_base[NCH * NC4];   // 8 MB: exclusive bases (seeded)
__device__ float4 g_carry[NC4];        // 32 KB: carry across segments
__device__ float  g_rcp[TT * NB];      // 256 KB: 1/(t+1+len_n), [t][n]

__device__ __forceinline__ float4 f4add(float4 a, float4 b) {
    return make_float4(a.x + b.x, a.y + b.y, a.z + b.z, a.w + b.w);
}
__device__ __forceinline__ float4 f4shfl_up(float4 v, int off) {
    v.x = __shfl_up_sync(0xffffffffu, v.x, off);
    v.y = __shfl_up_sync(0xffffffffu, v.y, off);
    v.z = __shfl_up_sync(0xffffffffu, v.z, off);
    v.w = __shfl_up_sync(0xffffffffu, v.w, off);
    return v;
}

// Sum role: per-(chunk, col4) partial sums. __ldcg: bypass L1, keep in L2
// so the scanOut role two launches later re-reads as L2 hits.
__device__ __forceinline__ void sum_role(const float4* __restrict__ x4,
                                         int idx, int seg) {
    int nc4 = idx & (NC4 - 1);
    int gc = seg * CPS + (idx >> 11);
    const float4* p = x4 + (size_t)gc * CHUNK * NC4 + nc4;
    float4 s = make_float4(0.f, 0.f, 0.f, 0.f);
#pragma unroll
    for (int i = 0; i < CHUNK; i++) s = f4add(s, __ldcg(p + (size_t)i * NC4));
    g_agg[gc * NC4 + nc4] = s;
}

// kscan role: warp-per-column shfl scan of segment seg's 64 chunk aggregates.
__device__ __forceinline__ void kscan_role(const int* __restrict__ cached_len,
                                           const float4* __restrict__ avg4,
                                           int widx, int seg) {
    int col4 = widx >> 5;                  // 0 .. NC4-1
    int lane = widx & 31;

    float4 carry;
    if (seg == 0) {
        float lenf = (float)cached_len[col4 >> 7];
        float4 a = avg4[col4];
        carry = make_float4(a.x * lenf, a.y * lenf, a.z * lenf, a.w * lenf);
    } else {
        carry = g_carry[col4];
    }

    int gc0 = seg * CPS;
    float4 a0 = g_agg[(gc0 + 2 * lane)     * NC4 + col4];
    float4 a1 = g_agg[(gc0 + 2 * lane + 1) * NC4 + col4];
    float4 incl = f4add(a0, a1);
#pragma unroll
    for (int off = 1; off < 32; off <<= 1) {
        float4 up = f4shfl_up(incl, off);
        if (lane >= off) incl = f4add(incl, up);
    }
    float4 excl = f4shfl_up(incl, 1);
    if (lane == 0) excl = make_float4(0.f, 0.f, 0.f, 0.f);

    float4 b0 = f4add(carry, excl);
    g_base[(gc0 + 2 * lane)     * NC4 + col4] = b0;
    g_base[(gc0 + 2 * lane + 1) * NC4 + col4] = f4add(b0, a0);
    if (lane == 31) g_carry[col4] = f4add(carry, incl);
}

// kA: sum(seg 0) + reciprocal table.
__global__ void __launch_bounds__(256)
kA(const float4* __restrict__ x4, const int* __restrict__ cached_len) {
    int bid = blockIdx.x, tid = threadIdx.x;
    if (bid < ROLE_BLOCKS) {
        sum_role(x4, bid * 256 + tid, 0);
    } else {
        int idx = (bid - ROLE_BLOCKS) * 256 + tid;     // 0 .. TT*NB-1
        int n = idx & (NB - 1);
        int t = idx >> 4;
        g_rcp[idx] = 1.0f / ((float)(t + 1) + (float)cached_len[n]);
    }
}

// kFused(s): [0,b_sum): sum(s+2) | [b_sum,b_scan): scanOut(s) | rest: kscan(s+1).
__global__ void __launch_bounds__(256)
kFused(const float4* __restrict__ x4, const int* __restrict__ cached_len,
       const float4* __restrict__ avg4, float4* __restrict__ out4,
       int s, int b_sum, int b_scan, int extras) {
    int bid = blockIdx.x, tid = threadIdx.x;

    if (bid < b_sum) {                                   // DRAM stream: seg s+2
        sum_role(x4, bid * 256 + tid, s + 2);
        return;
    }
    if (bid >= b_scan) {                                 // tiny: base scan seg s+1
        kscan_role(cached_len, avg4, (bid - b_scan) * 256 + tid, s + 1);
        return;
    }

    // scanOut role: segment s (x[s] L2-hot from two launches ago).
    int idx = (bid - b_sum) * 256 + tid;
    int nc4 = idx & (NC4 - 1);
    int gc = s * CPS + (idx >> 11);
    int n = nc4 >> 7;                                    // warp-uniform

    float4 run = g_base[gc * NC4 + nc4];
    const float4* px = x4   + (size_t)gc * CHUNK * NC4 + nc4;
    float4*       po = out4 + (size_t)gc * CHUNK * NC4 + nc4;
    const float*  pr = g_rcp + (size_t)gc * CHUNK * NB + n;

    float4 last = make_float4(0.f, 0.f, 0.f, 0.f);
#pragma unroll
    for (int i = 0; i < CHUNK; i++) {
        float4 v = __ldcs(px + (size_t)i * NC4);         // hit-then-evict (dead data)
        run = f4add(run, v);
        float r = pr[(size_t)i * NB];
        last.x = run.x * r; last.y = run.y * r;
        last.z = run.z * r; last.w = run.w * r;
        __stcs(po + (size_t)i * NC4, last);              // streaming store, no L2 pollution
    }

    if (extras && s == NSEG - 1) {
        // Tuple order: [new_x | new_cached_len (as float) | new_cached_avg]
        if ((idx >> 11) == CPS - 1)
            out4[(TOTAL + NB) / 4 + nc4] = last;         // new_x[T-1]
        if (idx < NB) {
            float* outf = (float*)out4;
            outf[TOTAL + idx] = (float)(cached_len[idx] + TT);
        }
    }
}

extern "C" void kernel_launch(void* const* d_in, const int* in_sizes, int n_in,
                              void* d_out, int out_size) {
    const float4* x4         = (const float4*)d_in[0];   // (T, N, C)
    const int*    cached_len = (const int*)d_in[1];      // (N,)
    const float4* avg4       = (const float4*)d_in[2];   // (N, C)
    float4* out4 = (float4*)d_out;

    int extras = (out_size >= TOTAL + NB + NC) ? 1 : 0;

    // LA: sum(0) + rcp
    kA<<<ROLE_BLOCKS + RCP_BLOCKS, 256>>>(x4, cached_len);
    // LB: sum(1) + kscan(0)   (s = -1: no scan role)
    kFused<<<ROLE_BLOCKS + KSCAN_BLOCKS, 256>>>(x4, cached_len, avg4, out4,
                                                -1, ROLE_BLOCKS, ROLE_BLOCKS, extras);
    // L(s), s=0..3: sum(s+2) + scanOut(s) + kscan(s+1)
    for (int s = 0; s < NSEG; s++) {
        int nb_sum   = (s + 2 < NSEG) ? ROLE_BLOCKS : 0;
        int nb_kscan = (s + 1 < NSEG) ? KSCAN_BLOCKS : 0;
        int b_scan = nb_sum + ROLE_BLOCKS;
        kFused<<<b_scan + nb_kscan, 256>>>(x4, cached_len, avg4, out4,
                                           s, nb_sum, b_scan, extras);
    }
}